// round 2
// baseline (speedup 1.0000x reference)
#include <cuda_runtime.h>
#include <math.h>

#define TPB     256
#define ROWSB   64
#define HID     192
#define G4      768
#define TSTEPS  20
#define NBATCH  131072
#define PSTR    388   // packed w row stride in floats (2-way max bank grouping)

#define W_S_FLOATS (96 * PSTR)
#define H_S_FLOATS (ROWSB * HID)
#define SMEM_FLOATS (W_S_FLOATS + H_S_FLOATS + ROWSB*2 + G4*2 + G4 + 2*HID + 2)
#define SMEM_BYTES  (SMEM_FLOATS * 4)

// ---- f32x2 packed helpers (FFMA2 only reachable via PTX on sm_103a) ----
__device__ __forceinline__ unsigned long long pack2(float lo, float hi) {
    unsigned long long r;
    asm("mov.b64 %0, {%1, %2};" : "=l"(r) : "f"(lo), "f"(hi));
    return r;
}
__device__ __forceinline__ unsigned long long splat2(float x) {
    unsigned long long r;
    asm("mov.b64 %0, {%1, %1};" : "=l"(r) : "f"(x));
    return r;
}
__device__ __forceinline__ void unpack2(unsigned long long v, float& lo, float& hi) {
    asm("mov.b64 {%0, %1}, %2;" : "=f"(lo), "=f"(hi) : "l"(v));
}
__device__ __forceinline__ void ffma2(unsigned long long& d,
                                      unsigned long long a, unsigned long long b) {
    asm("fma.rn.f32x2 %0, %1, %2, %0;" : "+l"(d) : "l"(a), "l"(b));
}

__device__ __forceinline__ float sigmoidf_(float x) {
    float e = __expf(-x);                  // x<<0: e=inf -> 0 ; x>>0: e=0 -> 1
    return __fdividef(1.f, 1.f + e);
}
__device__ __forceinline__ float tanhf_(float x) {
    float ax = fabsf(x);
    float e  = __expf(-2.f * ax);          // e in (0,1], no overflow
    float r  = (1.f - e) * __fdividef(1.f, 1.f + e);
    return copysignf(r, x);
}

__global__ void __launch_bounds__(TPB, 1)
lstm_dec(const float* __restrict__ obs,    // [20][N][2]
         const float* __restrict__ h0,     // [N][192]
         const float* __restrict__ w_ih,   // [768][2]
         const float* __restrict__ w_hh,   // [768][192]
         const float* __restrict__ b_ih,   // [768]
         const float* __restrict__ b_hh,   // [768]
         const float* __restrict__ w_out,  // [2][192]
         const float* __restrict__ b_out,  // [2]
         float* __restrict__ out)          // [20][N][2]
{
    extern __shared__ float sm[];
    float* w_s    = sm;                     // 96 pair-rows x PSTR, (q,q+1) interleaved
    float* h_s    = w_s    + W_S_FLOATS;    // [64][192]
    float* x_s    = h_s    + H_S_FLOATS;    // [64][2]
    float* wih_s  = x_s    + ROWSB*2;       // [768][2]
    float* bias_s = wih_s  + G4*2;          // [768] = b_ih + b_hh
    float* wout_s = bias_s + G4;            // [2][192]
    float* bout_s = wout_s + 2*HID;         // [2]

    const int tid = threadIdx.x;
    const int tg  = tid & 15;               // gate group (16)
    const int tr  = tid >> 4;               // row group  (16), 4 rows each
    const size_t rowg = (size_t)blockIdx.x * ROWSB;

    // ---- one-time staging ----
    for (int i = tid; i < H_S_FLOATS/4; i += TPB)
        reinterpret_cast<float4*>(h_s)[i] =
            reinterpret_cast<const float4*>(h0 + rowg*HID)[i];
    for (int i = tid; i < G4; i += TPB) {
        bias_s[i]     = b_ih[i] + b_hh[i];
        wih_s[2*i+0]  = w_ih[2*i+0];
        wih_s[2*i+1]  = w_ih[2*i+1];
    }
    for (int i = tid; i < 2*HID; i += TPB) wout_s[i] = w_out[i];
    if (tid < 2) bout_s[tid] = b_out[tid];

    float c_reg[4][4][3];    // [row][chunk][j]
    float hn_reg[4][4][3];
#pragma unroll
    for (int r = 0; r < 4; r++)
#pragma unroll
        for (int ch = 0; ch < 4; ch++)
#pragma unroll
            for (int j = 0; j < 3; j++) c_reg[r][ch][j] = 0.f;

    int woff[2][3];
#pragma unroll
    for (int qp = 0; qp < 2; qp++)
#pragma unroll
        for (int j = 0; j < 3; j++)
            woff[qp][j] = (qp*48 + tg*3 + j) * PSTR;
    int hoff[4];
#pragma unroll
    for (int r = 0; r < 4; r++) hoff[r] = (tr*4 + r) * HID;

    for (int t = 0; t < TSTEPS; t++) {
        const int it = (t == 0) ? 0 : (t - 1);   // xs index: [0,0,1,...,18]

        for (int ch = 0; ch < 4; ch++) {
            __syncthreads();   // prior users of w_s / x_s are done
            // stage w chunk: global gate rows {q*192 + ch*48 + jj}, packed (q0,q1)/(q2,q3)
            for (int i = tid; i < 192*48; i += TPB) {
                const int lrow = i / 48;
                const int c4   = i - lrow*48;
                const int q    = lrow / 48;
                const int jj   = lrow - q*48;
                const float4 v = *reinterpret_cast<const float4*>(
                    w_hh + (size_t)(q*192 + ch*48 + jj)*HID + c4*4);
                float* dst = w_s + ((q >> 1)*48 + jj)*PSTR + c4*8 + (q & 1);
                dst[0] = v.x; dst[2] = v.y; dst[4] = v.z; dst[6] = v.w;
            }
            if (ch == 0 && tid < ROWSB*2)
                x_s[tid] = obs[((size_t)it*NBATCH + rowg)*2 + tid];
            __syncthreads();

            // acc init: x @ Wih^T + (b_ih + b_hh), packed (i,f) and (g,o)
            unsigned long long acc[2][3][4];
#pragma unroll
            for (int r = 0; r < 4; r++) {
                const float x0 = x_s[(tr*4 + r)*2 + 0];
                const float x1 = x_s[(tr*4 + r)*2 + 1];
#pragma unroll
                for (int qp = 0; qp < 2; qp++)
#pragma unroll
                    for (int j = 0; j < 3; j++) {
                        const int g0 = (2*qp)*192 + ch*48 + tg*3 + j;
                        const int g1 = g0 + 192;
                        const float a0 = fmaf(x0, wih_s[2*g0],
                                         fmaf(x1, wih_s[2*g0+1], bias_s[g0]));
                        const float a1 = fmaf(x0, wih_s[2*g1],
                                         fmaf(x1, wih_s[2*g1+1], bias_s[g1]));
                        acc[qp][j][r] = pack2(a0, a1);
                    }
            }

            // K sweep: acc += h_old[k] * w[gatepair][k]  (packed f32x2)
#pragma unroll 2
            for (int k = 0; k < HID; k += 4) {
                unsigned long long hsp[4][4];
#pragma unroll
                for (int r = 0; r < 4; r++) {
                    const float4 hv = *reinterpret_cast<const float4*>(h_s + hoff[r] + k);
                    hsp[r][0] = splat2(hv.x); hsp[r][1] = splat2(hv.y);
                    hsp[r][2] = splat2(hv.z); hsp[r][3] = splat2(hv.w);
                }
#pragma unroll
                for (int qp = 0; qp < 2; qp++)
#pragma unroll
                    for (int j = 0; j < 3; j++) {
                        const float* wp = w_s + woff[qp][j] + k*2;
                        const ulonglong2 wA = *reinterpret_cast<const ulonglong2*>(wp);
                        const ulonglong2 wB = *reinterpret_cast<const ulonglong2*>(wp + 4);
#pragma unroll
                        for (int r = 0; r < 4; r++) {
                            ffma2(acc[qp][j][r], hsp[r][0], wA.x);
                            ffma2(acc[qp][j][r], hsp[r][1], wA.y);
                            ffma2(acc[qp][j][r], hsp[r][2], wB.x);
                            ffma2(acc[qp][j][r], hsp[r][3], wB.y);
                        }
                    }
            }

            // activations + state update for this hidden chunk
#pragma unroll
            for (int r = 0; r < 4; r++)
#pragma unroll
                for (int j = 0; j < 3; j++) {
                    float iv, fv, gv, ov;
                    unpack2(acc[0][j][r], iv, fv);
                    unpack2(acc[1][j][r], gv, ov);
                    iv = sigmoidf_(iv); fv = sigmoidf_(fv);
                    gv = tanhf_(gv);    ov = sigmoidf_(ov);
                    const float cn = fmaf(fv, c_reg[r][ch][j], iv * gv);
                    c_reg[r][ch][j]  = cn;
                    hn_reg[r][ch][j] = ov * tanhf_(cn);
                }
        } // ch

        __syncthreads();   // all reads of h_old complete
#pragma unroll
        for (int r = 0; r < 4; r++)
#pragma unroll
            for (int ch = 0; ch < 4; ch++)
#pragma unroll
                for (int j = 0; j < 3; j++)
                    h_s[hoff[r] + ch*48 + tg*3 + j] = hn_reg[r][ch][j];
        __syncthreads();   // h_new visible

        // out[t] = h_new @ w_out^T + b_out
        if (tid < ROWSB*2) {
            const int r  = tid >> 1, cc = tid & 1;
            const float* hp = h_s + r*HID;
            const float* wp = wout_s + cc*HID;
            float s0 = 0.f, s1 = 0.f, s2 = 0.f, s3 = 0.f;
#pragma unroll
            for (int k = 0; k < HID; k += 4) {
                s0 = fmaf(hp[k+0], wp[k+0], s0);
                s1 = fmaf(hp[k+1], wp[k+1], s1);
                s2 = fmaf(hp[k+2], wp[k+2], s2);
                s3 = fmaf(hp[k+3], wp[k+3], s3);
            }
            out[((size_t)t*NBATCH + rowg + r)*2 + cc] = (s0+s1) + (s2+s3) + bout_s[cc];
        }
    }
}

extern "C" void kernel_launch(void* const* d_in, const int* in_sizes, int n_in,
                              void* d_out, int out_size)
{
    const float* obs   = (const float*)d_in[0];
    const float* h0    = (const float*)d_in[1];
    const float* w_ih  = (const float*)d_in[2];
    const float* w_hh  = (const float*)d_in[3];
    const float* b_ih  = (const float*)d_in[4];
    const float* b_hh  = (const float*)d_in[5];
    const float* w_out = (const float*)d_in[6];
    const float* b_out = (const float*)d_in[7];
    float* out = (float*)d_out;

    cudaFuncSetAttribute(lstm_dec, cudaFuncAttributeMaxDynamicSharedMemorySize,
                         SMEM_BYTES);
    lstm_dec<<<NBATCH / ROWSB, TPB, SMEM_BYTES>>>(obs, h0, w_ih, w_hh,
                                                  b_ih, b_hh, w_out, b_out, out);
}

// round 3
// speedup vs baseline: 1.0002x; 1.0002x over previous
#include <cuda_runtime.h>
#include <math.h>

#define TPB     256
#define ROWSB   64
#define HID     192
#define G4      768
#define TSTEPS  20
#define NBATCH  131072
#define PSTR    388   // packed w row stride in floats (2-way max bank grouping)

#define W_S_FLOATS (96 * PSTR)
#define H_S_FLOATS (ROWSB * HID)
#define SMEM_FLOATS (W_S_FLOATS + H_S_FLOATS + ROWSB*2 + G4*2 + G4 + 2*HID + 2)
#define SMEM_BYTES  (SMEM_FLOATS * 4)

// ---- f32x2 packed helpers (FFMA2 only reachable via PTX on sm_103a) ----
__device__ __forceinline__ unsigned long long pack2(float lo, float hi) {
    unsigned long long r;
    asm("mov.b64 %0, {%1, %2};" : "=l"(r) : "f"(lo), "f"(hi));
    return r;
}
__device__ __forceinline__ unsigned long long splat2(float x) {
    unsigned long long r;
    asm("mov.b64 %0, {%1, %1};" : "=l"(r) : "f"(x));
    return r;
}
__device__ __forceinline__ void unpack2(unsigned long long v, float& lo, float& hi) {
    asm("mov.b64 {%0, %1}, %2;" : "=f"(lo), "=f"(hi) : "l"(v));
}
__device__ __forceinline__ void ffma2(unsigned long long& d,
                                      unsigned long long a, unsigned long long b) {
    asm("fma.rn.f32x2 %0, %1, %2, %0;" : "+l"(d) : "l"(a), "l"(b));
}

__device__ __forceinline__ float sigmoidf_(float x) {
    float e = __expf(-x);                  // x<<0: e=inf -> 0 ; x>>0: e=0 -> 1
    return __fdividef(1.f, 1.f + e);
}
__device__ __forceinline__ float tanhf_(float x) {
    float ax = fabsf(x);
    float e  = __expf(-2.f * ax);          // e in (0,1], no overflow
    float r  = (1.f - e) * __fdividef(1.f, 1.f + e);
    return copysignf(r, x);
}

__global__ void __launch_bounds__(TPB, 1)
lstm_dec(const float* __restrict__ obs,    // [20][N][2]
         const float* __restrict__ h0,     // [N][192]
         const float* __restrict__ w_ih,   // [768][2]
         const float* __restrict__ w_hh,   // [768][192]
         const float* __restrict__ b_ih,   // [768]
         const float* __restrict__ b_hh,   // [768]
         const float* __restrict__ w_out,  // [2][192]
         const float* __restrict__ b_out,  // [2]
         float* __restrict__ out)          // [20][N][2]
{
    extern __shared__ float sm[];
    float* w_s    = sm;                     // 96 pair-rows x PSTR, (q,q+1) interleaved
    float* h_s    = w_s    + W_S_FLOATS;    // [64][192]
    float* x_s    = h_s    + H_S_FLOATS;    // [64][2]
    float* wih_s  = x_s    + ROWSB*2;       // [768][2]
    float* bias_s = wih_s  + G4*2;          // [768] = b_ih + b_hh
    float* wout_s = bias_s + G4;            // [2][192]
    float* bout_s = wout_s + 2*HID;         // [2]

    const int tid = threadIdx.x;
    const int tg  = tid & 15;               // gate group (16)
    const int tr  = tid >> 4;               // row group  (16), 4 rows each
    const size_t rowg = (size_t)blockIdx.x * ROWSB;

    // ---- one-time staging ----
    for (int i = tid; i < H_S_FLOATS/4; i += TPB)
        reinterpret_cast<float4*>(h_s)[i] =
            reinterpret_cast<const float4*>(h0 + rowg*HID)[i];
    for (int i = tid; i < G4; i += TPB) {
        bias_s[i]     = b_ih[i] + b_hh[i];
        wih_s[2*i+0]  = w_ih[2*i+0];
        wih_s[2*i+1]  = w_ih[2*i+1];
    }
    for (int i = tid; i < 2*HID; i += TPB) wout_s[i] = w_out[i];
    if (tid < 2) bout_s[tid] = b_out[tid];

    float c_reg[4][4][3];    // [row][chunk][j]
    float hn_reg[4][4][3];
#pragma unroll
    for (int r = 0; r < 4; r++)
#pragma unroll
        for (int ch = 0; ch < 4; ch++)
#pragma unroll
            for (int j = 0; j < 3; j++) c_reg[r][ch][j] = 0.f;

    int woff[2][3];
#pragma unroll
    for (int qp = 0; qp < 2; qp++)
#pragma unroll
        for (int j = 0; j < 3; j++)
            woff[qp][j] = (qp*48 + tg*3 + j) * PSTR;
    int hoff[4];
#pragma unroll
    for (int r = 0; r < 4; r++) hoff[r] = (tr*4 + r) * HID;

    for (int t = 0; t < TSTEPS; t++) {
        const int it = (t == 0) ? 0 : (t - 1);   // xs index: [0,0,1,...,18]

        for (int ch = 0; ch < 4; ch++) {
            __syncthreads();   // prior users of w_s / x_s are done
            // stage w chunk: global gate rows {q*192 + ch*48 + jj}, packed (q0,q1)/(q2,q3)
            for (int i = tid; i < 192*48; i += TPB) {
                const int lrow = i / 48;
                const int c4   = i - lrow*48;
                const int q    = lrow / 48;
                const int jj   = lrow - q*48;
                const float4 v = *reinterpret_cast<const float4*>(
                    w_hh + (size_t)(q*192 + ch*48 + jj)*HID + c4*4);
                float* dst = w_s + ((q >> 1)*48 + jj)*PSTR + c4*8 + (q & 1);
                dst[0] = v.x; dst[2] = v.y; dst[4] = v.z; dst[6] = v.w;
            }
            if (ch == 0 && tid < ROWSB*2)
                x_s[tid] = obs[((size_t)it*NBATCH + rowg)*2 + tid];
            __syncthreads();

            // acc init: x @ Wih^T + (b_ih + b_hh), packed (i,f) and (g,o)
            unsigned long long acc[2][3][4];
#pragma unroll
            for (int r = 0; r < 4; r++) {
                const float x0 = x_s[(tr*4 + r)*2 + 0];
                const float x1 = x_s[(tr*4 + r)*2 + 1];
#pragma unroll
                for (int qp = 0; qp < 2; qp++)
#pragma unroll
                    for (int j = 0; j < 3; j++) {
                        const int g0 = (2*qp)*192 + ch*48 + tg*3 + j;
                        const int g1 = g0 + 192;
                        const float a0 = fmaf(x0, wih_s[2*g0],
                                         fmaf(x1, wih_s[2*g0+1], bias_s[g0]));
                        const float a1 = fmaf(x0, wih_s[2*g1],
                                         fmaf(x1, wih_s[2*g1+1], bias_s[g1]));
                        acc[qp][j][r] = pack2(a0, a1);
                    }
            }

            // K sweep: acc += h_old[k] * w[gatepair][k]  (packed f32x2)
#pragma unroll 2
            for (int k = 0; k < HID; k += 4) {
                unsigned long long hsp[4][4];
#pragma unroll
                for (int r = 0; r < 4; r++) {
                    const float4 hv = *reinterpret_cast<const float4*>(h_s + hoff[r] + k);
                    hsp[r][0] = splat2(hv.x); hsp[r][1] = splat2(hv.y);
                    hsp[r][2] = splat2(hv.z); hsp[r][3] = splat2(hv.w);
                }
#pragma unroll
                for (int qp = 0; qp < 2; qp++)
#pragma unroll
                    for (int j = 0; j < 3; j++) {
                        const float* wp = w_s + woff[qp][j] + k*2;
                        const ulonglong2 wA = *reinterpret_cast<const ulonglong2*>(wp);
                        const ulonglong2 wB = *reinterpret_cast<const ulonglong2*>(wp + 4);
#pragma unroll
                        for (int r = 0; r < 4; r++) {
                            ffma2(acc[qp][j][r], hsp[r][0], wA.x);
                            ffma2(acc[qp][j][r], hsp[r][1], wA.y);
                            ffma2(acc[qp][j][r], hsp[r][2], wB.x);
                            ffma2(acc[qp][j][r], hsp[r][3], wB.y);
                        }
                    }
            }

            // activations + state update for this hidden chunk
#pragma unroll
            for (int r = 0; r < 4; r++)
#pragma unroll
                for (int j = 0; j < 3; j++) {
                    float iv, fv, gv, ov;
                    unpack2(acc[0][j][r], iv, fv);
                    unpack2(acc[1][j][r], gv, ov);
                    iv = sigmoidf_(iv); fv = sigmoidf_(fv);
                    gv = tanhf_(gv);    ov = sigmoidf_(ov);
                    const float cn = fmaf(fv, c_reg[r][ch][j], iv * gv);
                    c_reg[r][ch][j]  = cn;
                    hn_reg[r][ch][j] = ov * tanhf_(cn);
                }
        } // ch

        __syncthreads();   // all reads of h_old complete
#pragma unroll
        for (int r = 0; r < 4; r++)
#pragma unroll
            for (int ch = 0; ch < 4; ch++)
#pragma unroll
                for (int j = 0; j < 3; j++)
                    h_s[hoff[r] + ch*48 + tg*3 + j] = hn_reg[r][ch][j];
        __syncthreads();   // h_new visible

        // out[t] = h_new @ w_out^T + b_out
        if (tid < ROWSB*2) {
            const int r  = tid >> 1, cc = tid & 1;
            const float* hp = h_s + r*HID;
            const float* wp = wout_s + cc*HID;
            float s0 = 0.f, s1 = 0.f, s2 = 0.f, s3 = 0.f;
#pragma unroll
            for (int k = 0; k < HID; k += 4) {
                s0 = fmaf(hp[k+0], wp[k+0], s0);
                s1 = fmaf(hp[k+1], wp[k+1], s1);
                s2 = fmaf(hp[k+2], wp[k+2], s2);
                s3 = fmaf(hp[k+3], wp[k+3], s3);
            }
            out[((size_t)t*NBATCH + rowg + r)*2 + cc] = (s0+s1) + (s2+s3) + bout_s[cc];
        }
    }
}

extern "C" void kernel_launch(void* const* d_in, const int* in_sizes, int n_in,
                              void* d_out, int out_size)
{
    const float* obs   = (const float*)d_in[0];
    const float* h0    = (const float*)d_in[1];
    const float* w_ih  = (const float*)d_in[2];
    const float* w_hh  = (const float*)d_in[3];
    const float* b_ih  = (const float*)d_in[4];
    const float* b_hh  = (const float*)d_in[5];
    const float* w_out = (const float*)d_in[6];
    const float* b_out = (const float*)d_in[7];
    float* out = (float*)d_out;

    cudaFuncSetAttribute(lstm_dec, cudaFuncAttributeMaxDynamicSharedMemorySize,
                         SMEM_BYTES);
    lstm_dec<<<NBATCH / ROWSB, TPB, SMEM_BYTES>>>(obs, h0, w_ih, w_hh,
                                                  b_ih, b_hh, w_out, b_out, out);
}

// round 4
// speedup vs baseline: 1.0009x; 1.0008x over previous
#include <cuda_runtime.h>
#include <math.h>

#define TPB     256
#define ROWSB   64
#define HID     192
#define G4      768
#define TSTEPS  20
#define NBATCH  131072
#define PSTR    388   // packed w row stride in floats (2-way max bank grouping)

#define W_S_FLOATS (96 * PSTR)
#define H_S_FLOATS (ROWSB * HID)
#define SMEM_FLOATS (W_S_FLOATS + H_S_FLOATS + ROWSB*2 + G4*2 + G4 + 2*HID + 2)
#define SMEM_BYTES  (SMEM_FLOATS * 4)

// ---- f32x2 packed helpers (FFMA2 only reachable via PTX on sm_103a) ----
__device__ __forceinline__ unsigned long long pack2(float lo, float hi) {
    unsigned long long r;
    asm("mov.b64 %0, {%1, %2};" : "=l"(r) : "f"(lo), "f"(hi));
    return r;
}
__device__ __forceinline__ unsigned long long splat2(float x) {
    unsigned long long r;
    asm("mov.b64 %0, {%1, %1};" : "=l"(r) : "f"(x));
    return r;
}
__device__ __forceinline__ void unpack2(unsigned long long v, float& lo, float& hi) {
    asm("mov.b64 {%0, %1}, %2;" : "=f"(lo), "=f"(hi) : "l"(v));
}
__device__ __forceinline__ void ffma2(unsigned long long& d,
                                      unsigned long long a, unsigned long long b) {
    asm("fma.rn.f32x2 %0, %1, %2, %0;" : "+l"(d) : "l"(a), "l"(b));
}

__device__ __forceinline__ float sigmoidf_(float x) {
    float e = __expf(-x);                  // x<<0: e=inf -> 0 ; x>>0: e=0 -> 1
    return __fdividef(1.f, 1.f + e);
}
__device__ __forceinline__ float tanhf_(float x) {
    float ax = fabsf(x);
    float e  = __expf(-2.f * ax);          // e in (0,1], no overflow
    float r  = (1.f - e) * __fdividef(1.f, 1.f + e);
    return copysignf(r, x);
}

__global__ void __launch_bounds__(TPB, 1)
lstm_dec(const float* __restrict__ obs,    // [20][N][2]
         const float* __restrict__ h0,     // [N][192]
         const float* __restrict__ w_ih,   // [768][2]
         const float* __restrict__ w_hh,   // [768][192]
         const float* __restrict__ b_ih,   // [768]
         const float* __restrict__ b_hh,   // [768]
         const float* __restrict__ w_out,  // [2][192]
         const float* __restrict__ b_out,  // [2]
         float* __restrict__ out)          // [20][N][2]
{
    extern __shared__ float sm[];
    float* w_s    = sm;                     // 96 pair-rows x PSTR, (q,q+1) interleaved
    float* h_s    = w_s    + W_S_FLOATS;    // [64][192]
    float* x_s    = h_s    + H_S_FLOATS;    // [64][2]
    float* wih_s  = x_s    + ROWSB*2;       // [768][2]
    float* bias_s = wih_s  + G4*2;          // [768] = b_ih + b_hh
    float* wout_s = bias_s + G4;            // [2][192]
    float* bout_s = wout_s + 2*HID;         // [2]

    const int tid = threadIdx.x;
    const int tg  = tid & 15;               // gate group (16)
    const int tr  = tid >> 4;               // row group  (16), 4 rows each
    const size_t rowg = (size_t)blockIdx.x * ROWSB;

    // ---- one-time staging ----
    for (int i = tid; i < H_S_FLOATS/4; i += TPB)
        reinterpret_cast<float4*>(h_s)[i] =
            reinterpret_cast<const float4*>(h0 + rowg*HID)[i];
    for (int i = tid; i < G4; i += TPB) {
        bias_s[i]     = b_ih[i] + b_hh[i];
        wih_s[2*i+0]  = w_ih[2*i+0];
        wih_s[2*i+1]  = w_ih[2*i+1];
    }
    for (int i = tid; i < 2*HID; i += TPB) wout_s[i] = w_out[i];
    if (tid < 2) bout_s[tid] = b_out[tid];

    float c_reg[4][4][3];    // [row][chunk][j]
    float hn_reg[4][4][3];
#pragma unroll
    for (int r = 0; r < 4; r++)
#pragma unroll
        for (int ch = 0; ch < 4; ch++)
#pragma unroll
            for (int j = 0; j < 3; j++) c_reg[r][ch][j] = 0.f;

    int woff[2][3];
#pragma unroll
    for (int qp = 0; qp < 2; qp++)
#pragma unroll
        for (int j = 0; j < 3; j++)
            woff[qp][j] = (qp*48 + tg*3 + j) * PSTR;
    int hoff[4];
#pragma unroll
    for (int r = 0; r < 4; r++) hoff[r] = (tr*4 + r) * HID;

    for (int t = 0; t < TSTEPS; t++) {
        const int it = (t == 0) ? 0 : (t - 1);   // xs index: [0,0,1,...,18]

        for (int ch = 0; ch < 4; ch++) {
            __syncthreads();   // prior users of w_s / x_s are done
            // stage w chunk: global gate rows {q*192 + ch*48 + jj}, packed (q0,q1)/(q2,q3)
            for (int i = tid; i < 192*48; i += TPB) {
                const int lrow = i / 48;
                const int c4   = i - lrow*48;
                const int q    = lrow / 48;
                const int jj   = lrow - q*48;
                const float4 v = *reinterpret_cast<const float4*>(
                    w_hh + (size_t)(q*192 + ch*48 + jj)*HID + c4*4);
                float* dst = w_s + ((q >> 1)*48 + jj)*PSTR + c4*8 + (q & 1);
                dst[0] = v.x; dst[2] = v.y; dst[4] = v.z; dst[6] = v.w;
            }
            if (ch == 0 && tid < ROWSB*2)
                x_s[tid] = obs[((size_t)it*NBATCH + rowg)*2 + tid];
            __syncthreads();

            // acc init: x @ Wih^T + (b_ih + b_hh), packed (i,f) and (g,o)
            unsigned long long acc[2][3][4];
#pragma unroll
            for (int r = 0; r < 4; r++) {
                const float x0 = x_s[(tr*4 + r)*2 + 0];
                const float x1 = x_s[(tr*4 + r)*2 + 1];
#pragma unroll
                for (int qp = 0; qp < 2; qp++)
#pragma unroll
                    for (int j = 0; j < 3; j++) {
                        const int g0 = (2*qp)*192 + ch*48 + tg*3 + j;
                        const int g1 = g0 + 192;
                        const float a0 = fmaf(x0, wih_s[2*g0],
                                         fmaf(x1, wih_s[2*g0+1], bias_s[g0]));
                        const float a1 = fmaf(x0, wih_s[2*g1],
                                         fmaf(x1, wih_s[2*g1+1], bias_s[g1]));
                        acc[qp][j][r] = pack2(a0, a1);
                    }
            }

            // K sweep: acc += h_old[k] * w[gatepair][k]  (packed f32x2)
#pragma unroll 2
            for (int k = 0; k < HID; k += 4) {
                unsigned long long hsp[4][4];
#pragma unroll
                for (int r = 0; r < 4; r++) {
                    const float4 hv = *reinterpret_cast<const float4*>(h_s + hoff[r] + k);
                    hsp[r][0] = splat2(hv.x); hsp[r][1] = splat2(hv.y);
                    hsp[r][2] = splat2(hv.z); hsp[r][3] = splat2(hv.w);
                }
#pragma unroll
                for (int qp = 0; qp < 2; qp++)
#pragma unroll
                    for (int j = 0; j < 3; j++) {
                        const float* wp = w_s + woff[qp][j] + k*2;
                        const ulonglong2 wA = *reinterpret_cast<const ulonglong2*>(wp);
                        const ulonglong2 wB = *reinterpret_cast<const ulonglong2*>(wp + 4);
#pragma unroll
                        for (int r = 0; r < 4; r++) {
                            ffma2(acc[qp][j][r], hsp[r][0], wA.x);
                            ffma2(acc[qp][j][r], hsp[r][1], wA.y);
                            ffma2(acc[qp][j][r], hsp[r][2], wB.x);
                            ffma2(acc[qp][j][r], hsp[r][3], wB.y);
                        }
                    }
            }

            // activations + state update for this hidden chunk
#pragma unroll
            for (int r = 0; r < 4; r++)
#pragma unroll
                for (int j = 0; j < 3; j++) {
                    float iv, fv, gv, ov;
                    unpack2(acc[0][j][r], iv, fv);
                    unpack2(acc[1][j][r], gv, ov);
                    iv = sigmoidf_(iv); fv = sigmoidf_(fv);
                    gv = tanhf_(gv);    ov = sigmoidf_(ov);
                    const float cn = fmaf(fv, c_reg[r][ch][j], iv * gv);
                    c_reg[r][ch][j]  = cn;
                    hn_reg[r][ch][j] = ov * tanhf_(cn);
                }
        } // ch

        __syncthreads();   // all reads of h_old complete
#pragma unroll
        for (int r = 0; r < 4; r++)
#pragma unroll
            for (int ch = 0; ch < 4; ch++)
#pragma unroll
                for (int j = 0; j < 3; j++)
                    h_s[hoff[r] + ch*48 + tg*3 + j] = hn_reg[r][ch][j];
        __syncthreads();   // h_new visible

        // out[t] = h_new @ w_out^T + b_out
        if (tid < ROWSB*2) {
            const int r  = tid >> 1, cc = tid & 1;
            const float* hp = h_s + r*HID;
            const float* wp = wout_s + cc*HID;
            float s0 = 0.f, s1 = 0.f, s2 = 0.f, s3 = 0.f;
#pragma unroll
            for (int k = 0; k < HID; k += 4) {
                s0 = fmaf(hp[k+0], wp[k+0], s0);
                s1 = fmaf(hp[k+1], wp[k+1], s1);
                s2 = fmaf(hp[k+2], wp[k+2], s2);
                s3 = fmaf(hp[k+3], wp[k+3], s3);
            }
            out[((size_t)t*NBATCH + rowg + r)*2 + cc] = (s0+s1) + (s2+s3) + bout_s[cc];
        }
    }
}

extern "C" void kernel_launch(void* const* d_in, const int* in_sizes, int n_in,
                              void* d_out, int out_size)
{
    const float* obs   = (const float*)d_in[0];
    const float* h0    = (const float*)d_in[1];
    const float* w_ih  = (const float*)d_in[2];
    const float* w_hh  = (const float*)d_in[3];
    const float* b_ih  = (const float*)d_in[4];
    const float* b_hh  = (const float*)d_in[5];
    const float* w_out = (const float*)d_in[6];
    const float* b_out = (const float*)d_in[7];
    float* out = (float*)d_out;

    cudaFuncSetAttribute(lstm_dec, cudaFuncAttributeMaxDynamicSharedMemorySize,
                         SMEM_BYTES);
    lstm_dec<<<NBATCH / ROWSB, TPB, SMEM_BYTES>>>(obs, h0, w_ih, w_hh,
                                                  b_ih, b_hh, w_out, b_out, out);
}